// round 1
// baseline (speedup 1.0000x reference)
#include <cuda_runtime.h>

#define HH 224
#define WW 224
#define HW (HH*WW)
#define OH 448
#define OW 448
#define OHW (OH*OW)

// Scratch (static __device__ arrays — allocation-free per harness rules)
__device__ float g_x0[100 * HW];      // warped/concat input, 100 ch
__device__ float g_feats[500 * HW];   // head + 4 block outputs, 5*100 ch
__device__ float g_x36[36 * HW];      // w_last output
__device__ float g_smn[2 * HW];       // mask logits

// ---------------------------------------------------------------------------
// Kernel 1: bilinear warp of feat_0/feat_1 + concat feat_dense + flow -> g_x0
// ---------------------------------------------------------------------------
__global__ __launch_bounds__(256) void warp_concat_kernel(
    const float* __restrict__ f0, const float* __restrict__ f1,
    const float* __restrict__ fd, const float* __restrict__ flow)
{
    int p = blockIdx.x * 256 + threadIdx.x;
    if (p >= HW) return;
    int y = p / WW, x = p - y * WW;

    // channels 64..95 = feat_dense, 96..99 = flow
    #pragma unroll 4
    for (int c = 0; c < 32; c++) g_x0[(64 + c) * HW + p] = fd[c * HW + p];
    #pragma unroll
    for (int c = 0; c < 4; c++)  g_x0[(96 + c) * HW + p] = flow[c * HW + p];

    #pragma unroll
    for (int pair = 0; pair < 2; pair++) {
        const float* img = (pair == 0) ? f0 : f1;
        float px = (float)x + flow[(pair * 2 + 0) * HW + p];
        float py = (float)y + flow[(pair * 2 + 1) * HW + p];
        float fx = floorf(px), fy = floorf(py);
        float wx = px - fx, wy = py - fy;
        int ix = (int)fminf(fmaxf(fx, -2.f), 226.f);
        int iy = (int)fminf(fmaxf(fy, -2.f), 226.f);
        int x0i = min(max(ix, 0), WW - 1);
        int x1i = min(max(ix + 1, 0), WW - 1);
        int y0i = min(max(iy, 0), HH - 1);
        int y1i = min(max(iy + 1, 0), HH - 1);
        float w00 = (1.f - wx) * (1.f - wy);
        float w01 = wx * (1.f - wy);
        float w10 = (1.f - wx) * wy;
        float w11 = wx * wy;
        int b00 = y0i * WW + x0i, b01 = y0i * WW + x1i;
        int b10 = y1i * WW + x0i, b11 = y1i * WW + x1i;
        int cbase = pair * 32;
        #pragma unroll 4
        for (int c = 0; c < 32; c++) {
            const float* g = img + c * HW;
            g_x0[(cbase + c) * HW + p] =
                g[b00] * w00 + g[b01] * w01 + g[b10] * w10 + g[b11] * w11;
        }
    }
}

// ---------------------------------------------------------------------------
// Kernel 2: generic 3x3 conv, pad 1. Block = 32x8 output tile x OCT channels.
// MODE 0: head  -> out = prelu(conv, a) * mask
// MODE 1: block -> out = prelu(conv * mask, a)
// MODE 2: bias  -> out = conv + b
// ---------------------------------------------------------------------------
template <int CIN, int OCT, int MODE>
__global__ __launch_bounds__(256) void conv3x3_kernel(
    const float* __restrict__ in,    // [CIN][HW]
    const float* __restrict__ wgt,   // [cout][CIN][9]
    const float* __restrict__ aux,   // prelu a or bias
    const float* __restrict__ mask,  // [HW]
    float* __restrict__ out)         // writes [ocb+o][HW]
{
    __shared__ float s_in[10 * 34];
    __shared__ float s_w[OCT * 9];

    const int tid = threadIdx.x;
    const int tx = tid & 31;
    const int ty = tid >> 5;
    const int ox0 = blockIdx.x * 32;
    const int oy0 = blockIdx.y * 8;
    const int ocb = blockIdx.z * OCT;
    const int ox = ox0 + tx, oy = oy0 + ty;

    float acc[OCT];
    #pragma unroll
    for (int o = 0; o < OCT; o++) acc[o] = 0.f;

    for (int ci = 0; ci < CIN; ci++) {
        // stage input tile with halo (34x10), zero-padded
        #pragma unroll
        for (int idx = tid; idx < 340; idx += 256) {
            int r = idx / 34, c = idx - r * 34;
            int gy = oy0 - 1 + r, gx = ox0 - 1 + c;
            float v = 0.f;
            if (gx >= 0 && gx < WW && gy >= 0 && gy < HH)
                v = in[ci * HW + gy * WW + gx];
            s_in[idx] = v;
        }
        if (tid < OCT * 9)
            s_w[tid] = wgt[(ocb + tid / 9) * (CIN * 9) + ci * 9 + (tid % 9)];
        __syncthreads();

        float r[9];
        #pragma unroll
        for (int ky = 0; ky < 3; ky++)
            #pragma unroll
            for (int kx = 0; kx < 3; kx++)
                r[ky * 3 + kx] = s_in[(ty + ky) * 34 + tx + kx];

        #pragma unroll
        for (int o = 0; o < OCT; o++) {
            float s = acc[o];
            #pragma unroll
            for (int k = 0; k < 9; k++)
                s = fmaf(s_w[o * 9 + k], r[k], s);
            acc[o] = s;
        }
        __syncthreads();
    }

    float m = 0.f;
    if (MODE != 2) m = mask[oy * WW + ox];
    #pragma unroll
    for (int o = 0; o < OCT; o++) {
        float v = acc[o];
        if (MODE == 0) {
            float a = aux[ocb + o];
            v = (v >= 0.f) ? v : a * v;
            v *= m;
        } else if (MODE == 1) {
            v *= m;
            float a = aux[ocb + o];
            v = (v >= 0.f) ? v : a * v;
        } else {
            v += aux[ocb + o];
        }
        out[(ocb + o) * HW + oy * WW + ox] = v;
    }
}

// ---------------------------------------------------------------------------
// Kernel 3: 1x1 conv 500 -> 36 (w_last), weights staged in chunks of 100 cin
// ---------------------------------------------------------------------------
__global__ __launch_bounds__(256) void conv1x1_kernel(
    const float* __restrict__ feats, const float* __restrict__ wl,
    const float* __restrict__ bl, float* __restrict__ out)
{
    __shared__ float s_w[36 * 100];
    const int tid = threadIdx.x;
    const int p = blockIdx.x * 256 + tid;

    float acc[36];
    #pragma unroll
    for (int o = 0; o < 36; o++) acc[o] = bl[o];

    for (int ch = 0; ch < 5; ch++) {
        __syncthreads();
        for (int i = tid; i < 3600; i += 256) {
            int o = i / 100, ii = i - o * 100;
            s_w[i] = wl[o * 500 + ch * 100 + ii];
        }
        __syncthreads();
        const float* fp = feats + ch * 100 * HW + p;
        #pragma unroll 2
        for (int i = 0; i < 100; i++) {
            float v = fp[i * HW];
            #pragma unroll
            for (int o = 0; o < 36; o++)
                acc[o] = fmaf(s_w[o * 100 + i], v, acc[o]);
        }
    }
    #pragma unroll
    for (int o = 0; o < 36; o++) out[o * HW + p] = acc[o];
}

// ---------------------------------------------------------------------------
// Kernel 4: 2x bilinear upsample of x36 (36ch) -> out[0..36), plus mask_next
// jax.image.resize 'linear', 2x: even out idx -> taps (k-1,k) w (0.25,0.75),
// odd -> (k,k+1) w (0.75,0.25), clamped at edges (renormalization == clamp).
// ---------------------------------------------------------------------------
__global__ __launch_bounds__(256) void upsample_kernel(
    const float* __restrict__ x36, const float* __restrict__ smn,
    const float* __restrict__ smask, float* __restrict__ out)
{
    int p = blockIdx.x * 256 + threadIdx.x;
    if (p >= OHW) return;
    int oy = p / OW, ox = p - oy * OW;
    int iy = oy >> 1, ix = ox >> 1;

    int r0, r1; float wr0, wr1;
    if (oy & 1) { r0 = iy; r1 = min(iy + 1, HH - 1); wr0 = 0.75f; wr1 = 0.25f; }
    else        { r0 = max(iy - 1, 0); r1 = iy;      wr0 = 0.25f; wr1 = 0.75f; }
    int c0, c1; float wc0, wc1;
    if (ox & 1) { c0 = ix; c1 = min(ix + 1, WW - 1); wc0 = 0.75f; wc1 = 0.25f; }
    else        { c0 = max(ix - 1, 0); c1 = ix;      wc0 = 0.25f; wc1 = 0.75f; }

    int b00 = r0 * WW + c0, b01 = r0 * WW + c1;
    int b10 = r1 * WW + c0, b11 = r1 * WW + c1;

    #pragma unroll 4
    for (int ch = 0; ch < 36; ch++) {
        const float* g = x36 + ch * HW;
        float v = wr0 * (wc0 * g[b00] + wc1 * g[b01]) +
                  wr1 * (wc0 * g[b10] + wc1 * g[b11]);
        out[ch * OHW + p] = v;
    }

    const float* s0p = smn;
    const float* s1p = smn + HW;
    float s0 = wr0 * (wc0 * s0p[b00] + wc1 * s0p[b01]) +
               wr1 * (wc0 * s0p[b10] + wc1 * s0p[b11]);
    float s1 = wr0 * (wc0 * s1p[b00] + wc1 * s1p[b01]) +
               wr1 * (wc0 * s1p[b10] + wc1 * s1p[b11]);
    float mu = smask[iy * WW + ix];
    out[36 * OHW + p] = (s0 > s1) ? mu : 0.f;
}

// ---------------------------------------------------------------------------
// Launcher
// ---------------------------------------------------------------------------
extern "C" void kernel_launch(void* const* d_in, const int* in_sizes, int n_in,
                              void* d_out, int out_size)
{
    const float* feat_0     = (const float*)d_in[0];
    const float* feat_1     = (const float*)d_in[1];
    const float* feat_dense = (const float*)d_in[2];
    const float* flow       = (const float*)d_in[3];
    const float* space_mask = (const float*)d_in[4];
    const float* w_head     = (const float*)d_in[5];
    const float* a_head     = (const float*)d_in[6];
    const float* w_blocks   = (const float*)d_in[7];
    const float* a_blocks   = (const float*)d_in[8];
    const float* w_last     = (const float*)d_in[9];
    const float* b_last     = (const float*)d_in[10];
    const float* w_mask     = (const float*)d_in[11];
    const float* b_mask     = (const float*)d_in[12];

    float *x0, *feats, *x36, *smn;
    cudaGetSymbolAddress((void**)&x0,    g_x0);
    cudaGetSymbolAddress((void**)&feats, g_feats);
    cudaGetSymbolAddress((void**)&x36,   g_x36);
    cudaGetSymbolAddress((void**)&smn,   g_smn);

    // 1. warp + concat (100 ch input)
    warp_concat_kernel<<<196, 256>>>(feat_0, feat_1, feat_dense, flow);

    // 2. head conv + 4 blocks, outputs laid contiguously into g_feats
    dim3 cgrid(7, 28, 5);
    conv3x3_kernel<100, 20, 0><<<cgrid, 256>>>(
        x0, w_head, a_head, space_mask, feats);
    for (int i = 0; i < 4; i++) {
        conv3x3_kernel<100, 20, 1><<<cgrid, 256>>>(
            feats + i * 100 * HW,
            w_blocks + i * 100 * 100 * 9,
            a_blocks + i * 100,
            space_mask,
            feats + (i + 1) * 100 * HW);
    }

    // 3. 1x1 conv (w_last): 500 -> 36
    conv1x1_kernel<<<196, 256>>>(feats, w_last, b_last, x36);

    // 4. mask logits: 3x3 conv of x36 channels 4..35 -> 2 ch
    conv3x3_kernel<32, 2, 2><<<dim3(7, 28, 1), 256>>>(
        x36 + 4 * HW, w_mask, b_mask, space_mask, smn);

    // 5. 2x bilinear upsample (36 ch) + mask_next -> d_out
    upsample_kernel<<<784, 256>>>(x36, smn, space_mask, (float*)d_out);
}

// round 2
// speedup vs baseline: 2.0286x; 2.0286x over previous
#include <cuda_runtime.h>

#define HH 224
#define WW 224
#define HW (HH*WW)
#define OH 448
#define OW 448
#define OHW (OH*OW)

// Scratch
__device__ float g_x0[100 * HW];
__device__ float g_feats[500 * HW];
__device__ float g_x36[36 * HW];
__device__ float g_smn[2 * HW];

// ---------------------------------------------------------------------------
// f32x2 helpers (Blackwell packed fp32 SIMD2)
// ---------------------------------------------------------------------------
__device__ __forceinline__ unsigned long long pack2(float lo, float hi) {
    unsigned long long r;
    asm("mov.b64 %0, {%1, %2};" : "=l"(r) : "f"(lo), "f"(hi));
    return r;
}
__device__ __forceinline__ void unpack2(unsigned long long v, float& lo, float& hi) {
    asm("mov.b64 {%0, %1}, %2;" : "=f"(lo), "=f"(hi) : "l"(v));
}
__device__ __forceinline__ void ffma2(unsigned long long& acc,
                                      unsigned long long a, unsigned long long b) {
    asm("fma.rn.f32x2 %0, %1, %2, %0;" : "+l"(acc) : "l"(a), "l"(b));
}

// ---------------------------------------------------------------------------
// Kernel 1: bilinear warp + concat -> g_x0 (100 ch)
// ---------------------------------------------------------------------------
__global__ __launch_bounds__(256) void warp_concat_kernel(
    const float* __restrict__ f0, const float* __restrict__ f1,
    const float* __restrict__ fd, const float* __restrict__ flow)
{
    int p = blockIdx.x * 256 + threadIdx.x;
    if (p >= HW) return;
    int y = p / WW, x = p - y * WW;

    #pragma unroll 4
    for (int c = 0; c < 32; c++) g_x0[(64 + c) * HW + p] = fd[c * HW + p];
    #pragma unroll
    for (int c = 0; c < 4; c++)  g_x0[(96 + c) * HW + p] = flow[c * HW + p];

    #pragma unroll
    for (int pair = 0; pair < 2; pair++) {
        const float* img = (pair == 0) ? f0 : f1;
        float px = (float)x + flow[(pair * 2 + 0) * HW + p];
        float py = (float)y + flow[(pair * 2 + 1) * HW + p];
        float fx = floorf(px), fy = floorf(py);
        float wx = px - fx, wy = py - fy;
        int ix = (int)fminf(fmaxf(fx, -2.f), 226.f);
        int iy = (int)fminf(fmaxf(fy, -2.f), 226.f);
        int x0i = min(max(ix, 0), WW - 1);
        int x1i = min(max(ix + 1, 0), WW - 1);
        int y0i = min(max(iy, 0), HH - 1);
        int y1i = min(max(iy + 1, 0), HH - 1);
        float w00 = (1.f - wx) * (1.f - wy);
        float w01 = wx * (1.f - wy);
        float w10 = (1.f - wx) * wy;
        float w11 = wx * wy;
        int b00 = y0i * WW + x0i, b01 = y0i * WW + x1i;
        int b10 = y1i * WW + x0i, b11 = y1i * WW + x1i;
        int cbase = pair * 32;
        #pragma unroll 4
        for (int c = 0; c < 32; c++) {
            const float* g = img + c * HW;
            g_x0[(cbase + c) * HW + p] =
                g[b00] * w00 + g[b01] * w01 + g[b10] * w10 + g[b11] * w11;
        }
    }
}

// ---------------------------------------------------------------------------
// Kernel 2: big 3x3 conv, CIN=100, 20 out-ch (10 f32x2 pairs), tile 32x16,
// 2 vertical pixels/thread, 4 input channels staged per barrier.
// MODE 0: out = prelu(conv, a) * mask ; MODE 1: out = prelu(conv*mask, a)
// ---------------------------------------------------------------------------
#define NC 4
template <int MODE>
__global__ __launch_bounds__(256, 2) void conv3x3_f32x2_kernel(
    const float* __restrict__ in,    // [100][HW]
    const float* __restrict__ wgt,   // [oc][100][9]
    const float* __restrict__ aux,   // prelu a
    const float* __restrict__ mask,  // [HW]
    float* __restrict__ out)
{
    __shared__ __align__(16) float s_in[NC * 18 * 34];   // 18 rows x 34 cols per ch
    __shared__ __align__(16) float s_w[NC * 180];        // [c][pair][9][2] interleaved

    const int tid = threadIdx.x;
    const int tx = tid & 31;
    const int ty = tid >> 5;               // 0..7
    const int ox0 = blockIdx.x * 32;
    const int oy0 = blockIdx.y * 16;
    const int ocb = blockIdx.z * 20;
    const int ox = ox0 + tx;
    const int oyA = oy0 + ty * 2;          // pixel 0 row
    const int oyB = oyA + 1;               // pixel 1 row

    unsigned long long acc0[10], acc1[10];
    #pragma unroll
    for (int p = 0; p < 10; p++) { acc0[p] = 0ull; acc1[p] = 0ull; }

    for (int cb = 0; cb < 100; cb += NC) {
        __syncthreads();
        // --- stage NC input channels (34x18 halo tiles, zero padded) ---
        #pragma unroll
        for (int i = tid; i < NC * 612; i += 256) {
            int c = i / 612;
            int rem = i - c * 612;
            int r = rem / 34;
            int col = rem - r * 34;
            int gy = oy0 - 1 + r;
            int gx = ox0 - 1 + col;
            float v = 0.f;
            if (gx >= 0 && gx < WW && gy >= 0 && gy < HH)
                v = in[(cb + c) * HW + gy * WW + gx];
            s_in[i] = v;
        }
        // --- stage weights, oc-pair interleaved: s_w[c*180 + pr*18 + k*2 + par]
        #pragma unroll
        for (int i = tid; i < NC * 180; i += 256) {
            int c = i / 180;
            int rem = i - c * 180;
            int o = rem / 9;
            int k = rem - o * 9;
            s_w[c * 180 + (o >> 1) * 18 + k * 2 + (o & 1)] =
                wgt[(ocb + o) * 900 + (cb + c) * 9 + k];
        }
        __syncthreads();

        #pragma unroll
        for (int c = 0; c < NC; c++) {
            const float* si = s_in + c * 612 + (ty * 2) * 34 + tx;
            unsigned long long vd[12];
            #pragma unroll
            for (int r = 0; r < 4; r++)
                #pragma unroll
                for (int kx = 0; kx < 3; kx++) {
                    float v = si[r * 34 + kx];
                    vd[r * 3 + kx] = pack2(v, v);
                }
            const unsigned long long* wp =
                (const unsigned long long*)(s_w + c * 180);
            #pragma unroll
            for (int pr = 0; pr < 10; pr++) {
                #pragma unroll
                for (int k = 0; k < 9; k++) {
                    unsigned long long w2 = wp[pr * 9 + k];
                    ffma2(acc0[pr], w2, vd[k]);        // rows 0..2
                    ffma2(acc1[pr], w2, vd[k + 3]);    // rows 1..3
                }
            }
        }
    }

    float mA = mask[oyA * WW + ox];
    float mB = mask[oyB * WW + ox];
    #pragma unroll
    for (int pr = 0; pr < 10; pr++) {
        float v0A, v1A, v0B, v1B;
        unpack2(acc0[pr], v0A, v1A);
        unpack2(acc1[pr], v0B, v1B);
        float a0 = aux[ocb + pr * 2], a1 = aux[ocb + pr * 2 + 1];
        if (MODE == 0) {
            v0A = (v0A >= 0.f ? v0A : a0 * v0A) * mA;
            v1A = (v1A >= 0.f ? v1A : a1 * v1A) * mA;
            v0B = (v0B >= 0.f ? v0B : a0 * v0B) * mB;
            v1B = (v1B >= 0.f ? v1B : a1 * v1B) * mB;
        } else {
            v0A *= mA; v1A *= mA; v0B *= mB; v1B *= mB;
            v0A = (v0A >= 0.f ? v0A : a0 * v0A);
            v1A = (v1A >= 0.f ? v1A : a1 * v1A);
            v0B = (v0B >= 0.f ? v0B : a0 * v0B);
            v1B = (v1B >= 0.f ? v1B : a1 * v1B);
        }
        out[(ocb + pr * 2 + 0) * HW + oyA * WW + ox] = v0A;
        out[(ocb + pr * 2 + 1) * HW + oyA * WW + ox] = v1A;
        out[(ocb + pr * 2 + 0) * HW + oyB * WW + ox] = v0B;
        out[(ocb + pr * 2 + 1) * HW + oyB * WW + ox] = v1B;
    }
}

// ---------------------------------------------------------------------------
// Kernel 2b: small scalar 3x3 conv (mask head), CIN=32, OCT=2, bias only
// ---------------------------------------------------------------------------
template <int CIN, int OCT>
__global__ __launch_bounds__(256) void conv3x3_small_kernel(
    const float* __restrict__ in, const float* __restrict__ wgt,
    const float* __restrict__ bias, float* __restrict__ out)
{
    __shared__ float s_in[10 * 34];
    __shared__ float s_w[OCT * 9];

    const int tid = threadIdx.x;
    const int tx = tid & 31;
    const int ty = tid >> 5;
    const int ox0 = blockIdx.x * 32;
    const int oy0 = blockIdx.y * 8;
    const int ox = ox0 + tx, oy = oy0 + ty;

    float acc[OCT];
    #pragma unroll
    for (int o = 0; o < OCT; o++) acc[o] = 0.f;

    for (int ci = 0; ci < CIN; ci++) {
        #pragma unroll
        for (int idx = tid; idx < 340; idx += 256) {
            int r = idx / 34, c = idx - r * 34;
            int gy = oy0 - 1 + r, gx = ox0 - 1 + c;
            float v = 0.f;
            if (gx >= 0 && gx < WW && gy >= 0 && gy < HH)
                v = in[ci * HW + gy * WW + gx];
            s_in[idx] = v;
        }
        if (tid < OCT * 9)
            s_w[tid] = wgt[(tid / 9) * (CIN * 9) + ci * 9 + (tid % 9)];
        __syncthreads();

        float r[9];
        #pragma unroll
        for (int ky = 0; ky < 3; ky++)
            #pragma unroll
            for (int kx = 0; kx < 3; kx++)
                r[ky * 3 + kx] = s_in[(ty + ky) * 34 + tx + kx];

        #pragma unroll
        for (int o = 0; o < OCT; o++) {
            float s = acc[o];
            #pragma unroll
            for (int k = 0; k < 9; k++)
                s = fmaf(s_w[o * 9 + k], r[k], s);
            acc[o] = s;
        }
        __syncthreads();
    }
    #pragma unroll
    for (int o = 0; o < OCT; o++)
        out[o * HW + oy * WW + ox] = acc[o] + bias[o];
}

// ---------------------------------------------------------------------------
// Kernel 3: 1x1 conv 500 -> 36
// ---------------------------------------------------------------------------
__global__ __launch_bounds__(256) void conv1x1_kernel(
    const float* __restrict__ feats, const float* __restrict__ wl,
    const float* __restrict__ bl, float* __restrict__ out)
{
    __shared__ float s_w[36 * 100];
    const int tid = threadIdx.x;
    const int p = blockIdx.x * 256 + tid;

    float acc[36];
    #pragma unroll
    for (int o = 0; o < 36; o++) acc[o] = bl[o];

    for (int ch = 0; ch < 5; ch++) {
        __syncthreads();
        for (int i = tid; i < 3600; i += 256) {
            int o = i / 100, ii = i - o * 100;
            s_w[i] = wl[o * 500 + ch * 100 + ii];
        }
        __syncthreads();
        const float* fp = feats + ch * 100 * HW + p;
        #pragma unroll 2
        for (int i = 0; i < 100; i++) {
            float v = fp[i * HW];
            #pragma unroll
            for (int o = 0; o < 36; o++)
                acc[o] = fmaf(s_w[o * 100 + i], v, acc[o]);
        }
    }
    #pragma unroll
    for (int o = 0; o < 36; o++) out[o * HW + p] = acc[o];
}

// ---------------------------------------------------------------------------
// Kernel 4: 2x bilinear upsample + mask
// ---------------------------------------------------------------------------
__global__ __launch_bounds__(256) void upsample_kernel(
    const float* __restrict__ x36, const float* __restrict__ smn,
    const float* __restrict__ smask, float* __restrict__ out)
{
    int p = blockIdx.x * 256 + threadIdx.x;
    if (p >= OHW) return;
    int oy = p / OW, ox = p - oy * OW;
    int iy = oy >> 1, ix = ox >> 1;

    int r0, r1; float wr0, wr1;
    if (oy & 1) { r0 = iy; r1 = min(iy + 1, HH - 1); wr0 = 0.75f; wr1 = 0.25f; }
    else        { r0 = max(iy - 1, 0); r1 = iy;      wr0 = 0.25f; wr1 = 0.75f; }
    int c0, c1; float wc0, wc1;
    if (ox & 1) { c0 = ix; c1 = min(ix + 1, WW - 1); wc0 = 0.75f; wc1 = 0.25f; }
    else        { c0 = max(ix - 1, 0); c1 = ix;      wc0 = 0.25f; wc1 = 0.75f; }

    int b00 = r0 * WW + c0, b01 = r0 * WW + c1;
    int b10 = r1 * WW + c0, b11 = r1 * WW + c1;

    #pragma unroll 4
    for (int ch = 0; ch < 36; ch++) {
        const float* g = x36 + ch * HW;
        float v = wr0 * (wc0 * g[b00] + wc1 * g[b01]) +
                  wr1 * (wc0 * g[b10] + wc1 * g[b11]);
        out[ch * OHW + p] = v;
    }

    const float* s0p = smn;
    const float* s1p = smn + HW;
    float s0 = wr0 * (wc0 * s0p[b00] + wc1 * s0p[b01]) +
               wr1 * (wc0 * s0p[b10] + wc1 * s0p[b11]);
    float s1 = wr0 * (wc0 * s1p[b00] + wc1 * s1p[b01]) +
               wr1 * (wc0 * s1p[b10] + wc1 * s1p[b11]);
    float mu = smask[iy * WW + ix];
    out[36 * OHW + p] = (s0 > s1) ? mu : 0.f;
}

// ---------------------------------------------------------------------------
// Launcher
// ---------------------------------------------------------------------------
extern "C" void kernel_launch(void* const* d_in, const int* in_sizes, int n_in,
                              void* d_out, int out_size)
{
    const float* feat_0     = (const float*)d_in[0];
    const float* feat_1     = (const float*)d_in[1];
    const float* feat_dense = (const float*)d_in[2];
    const float* flow       = (const float*)d_in[3];
    const float* space_mask = (const float*)d_in[4];
    const float* w_head     = (const float*)d_in[5];
    const float* a_head     = (const float*)d_in[6];
    const float* w_blocks   = (const float*)d_in[7];
    const float* a_blocks   = (const float*)d_in[8];
    const float* w_last     = (const float*)d_in[9];
    const float* b_last     = (const float*)d_in[10];
    const float* w_mask     = (const float*)d_in[11];
    const float* b_mask     = (const float*)d_in[12];

    float *x0, *feats, *x36, *smn;
    cudaGetSymbolAddress((void**)&x0,    g_x0);
    cudaGetSymbolAddress((void**)&feats, g_feats);
    cudaGetSymbolAddress((void**)&x36,   g_x36);
    cudaGetSymbolAddress((void**)&smn,   g_smn);

    warp_concat_kernel<<<196, 256>>>(feat_0, feat_1, feat_dense, flow);

    dim3 cgrid(7, 14, 5);   // 32x16 tiles, 20 oc per z
    conv3x3_f32x2_kernel<0><<<cgrid, 256>>>(
        x0, w_head, a_head, space_mask, feats);
    for (int i = 0; i < 4; i++) {
        conv3x3_f32x2_kernel<1><<<cgrid, 256>>>(
            feats + i * 100 * HW,
            w_blocks + i * 100 * 100 * 9,
            a_blocks + i * 100,
            space_mask,
            feats + (i + 1) * 100 * HW);
    }

    conv1x1_kernel<<<196, 256>>>(feats, w_last, b_last, x36);

    conv3x3_small_kernel<32, 2><<<dim3(7, 28, 1), 256>>>(
        x36 + 4 * HW, w_mask, b_mask, smn);

    upsample_kernel<<<784, 256>>>(x36, smn, space_mask, (float*)d_out);
}

// round 3
// speedup vs baseline: 2.1454x; 1.0576x over previous
#include <cuda_runtime.h>

#define HH 224
#define WW 224
#define HW (HH*WW)
#define OH 448
#define OW 448
#define OHW (OH*OW)

// Scratch
__device__ float g_x0[100 * HW];
__device__ float g_feats[500 * HW];
__device__ float g_x36[36 * HW];
__device__ float g_smn[2 * HW];

// ---------------------------------------------------------------------------
// helpers
// ---------------------------------------------------------------------------
typedef unsigned long long u64;

__device__ __forceinline__ u64 pack2(float lo, float hi) {
    u64 r;
    asm("mov.b64 %0, {%1, %2};" : "=l"(r) : "f"(lo), "f"(hi));
    return r;
}
__device__ __forceinline__ void unpack2(u64 v, float& lo, float& hi) {
    asm("mov.b64 {%0, %1}, %2;" : "=f"(lo), "=f"(hi) : "l"(v));
}
__device__ __forceinline__ void ffma2(u64& acc, u64 a, u64 b) {
    asm("fma.rn.f32x2 %0, %1, %2, %0;" : "+l"(acc) : "l"(a), "l"(b));
}
__device__ __forceinline__ unsigned smem_u32(const void* p) {
    unsigned r;
    asm("{ .reg .u64 t; cvta.to.shared.u64 t, %1; cvt.u32.u64 %0, t; }"
        : "=r"(r) : "l"(p));
    return r;
}
__device__ __forceinline__ void cp16z(unsigned dst, const void* src, int srcsize) {
    asm volatile("cp.async.cg.shared.global [%0], [%1], 16, %2;"
                 :: "r"(dst), "l"(src), "r"(srcsize));
}
__device__ __forceinline__ void cp4(unsigned dst, const void* src) {
    asm volatile("cp.async.ca.shared.global [%0], [%1], 4;"
                 :: "r"(dst), "l"(src));
}
__device__ __forceinline__ void cp_commit() {
    asm volatile("cp.async.commit_group;");
}
template <int N>
__device__ __forceinline__ void cp_wait() {
    asm volatile("cp.async.wait_group %0;" :: "n"(N));
}

// ---------------------------------------------------------------------------
// Kernel 1: bilinear warp + concat -> g_x0 (100 ch)
// ---------------------------------------------------------------------------
__global__ __launch_bounds__(256) void warp_concat_kernel(
    const float* __restrict__ f0, const float* __restrict__ f1,
    const float* __restrict__ fd, const float* __restrict__ flow)
{
    int p = blockIdx.x * 256 + threadIdx.x;
    if (p >= HW) return;
    int y = p / WW, x = p - y * WW;

    #pragma unroll 4
    for (int c = 0; c < 32; c++) g_x0[(64 + c) * HW + p] = fd[c * HW + p];
    #pragma unroll
    for (int c = 0; c < 4; c++)  g_x0[(96 + c) * HW + p] = flow[c * HW + p];

    #pragma unroll
    for (int pair = 0; pair < 2; pair++) {
        const float* img = (pair == 0) ? f0 : f1;
        float px = (float)x + flow[(pair * 2 + 0) * HW + p];
        float py = (float)y + flow[(pair * 2 + 1) * HW + p];
        float fx = floorf(px), fy = floorf(py);
        float wx = px - fx, wy = py - fy;
        int ix = (int)fminf(fmaxf(fx, -2.f), 226.f);
        int iy = (int)fminf(fmaxf(fy, -2.f), 226.f);
        int x0i = min(max(ix, 0), WW - 1);
        int x1i = min(max(ix + 1, 0), WW - 1);
        int y0i = min(max(iy, 0), HH - 1);
        int y1i = min(max(iy + 1, 0), HH - 1);
        float w00 = (1.f - wx) * (1.f - wy);
        float w01 = wx * (1.f - wy);
        float w10 = (1.f - wx) * wy;
        float w11 = wx * wy;
        int b00 = y0i * WW + x0i, b01 = y0i * WW + x1i;
        int b10 = y1i * WW + x0i, b11 = y1i * WW + x1i;
        int cbase = pair * 32;
        #pragma unroll 4
        for (int c = 0; c < 32; c++) {
            const float* g = img + c * HW;
            g_x0[(cbase + c) * HW + p] =
                g[b00] * w00 + g[b01] * w01 + g[b10] * w10 + g[b11] * w11;
        }
    }
}

// ---------------------------------------------------------------------------
// Kernel 2: 3x3 conv, CIN=100, 10 out-ch (5 f32x2 pairs), tile 32x32,
// 4 vertical pixels/thread, NC=4 input channels per stage, cp.async
// double-buffered pipeline.
// MODE 0: out = prelu(conv, a) * mask ; MODE 1: out = prelu(conv*mask, a)
// ---------------------------------------------------------------------------
#define NC 4
#define TW 40                 // staged window width (floats), 16B aligned
#define TR 34                 // staged rows
#define CHF (TR * TW)         // floats per channel = 1360
#define NCHUNK (TR * 10)      // 16B chunks per channel = 340

template <int MODE>
__global__ __launch_bounds__(256, 2) void conv3x3_v2_kernel(
    const float* __restrict__ in,    // [100][HW]
    const float* __restrict__ wgt,   // [oc][100][9]
    const float* __restrict__ aux,   // prelu a
    const float* __restrict__ mask,  // [HW]
    float* __restrict__ out)
{
    __shared__ __align__(16) float s_in[2][NC * CHF];
    __shared__ __align__(16) float s_w[2][NC * 90];

    const int tid = threadIdx.x;
    const int tx = tid & 31;
    const int ty = tid >> 5;               // 0..7
    const int ox0 = blockIdx.x * 32;
    const int oy0 = blockIdx.y * 32;
    const int ocb = blockIdx.z * 10;
    const int ox = ox0 + tx;
    const int oyb = oy0 + ty * 4;

    u64 acc[20];
    #pragma unroll
    for (int i = 0; i < 20; i++) acc[i] = 0ull;

    // stage lambda (macro-style): stage cin block cb into buffer b
    auto stage = [&](int b, int cb) {
        // inputs: NC channels x 34 rows x 10 16B-chunks
        #pragma unroll
        for (int i = tid; i < NC * NCHUNK; i += 256) {
            int ch = i / NCHUNK;
            int rem = i - ch * NCHUNK;
            int r = rem / 10;
            int ck = rem - r * 10;
            int gy = oy0 - 1 + r;
            int gcol = ox0 - 4 + ck * 4;
            bool ok = (gy >= 0) && (gy < HH) && (gcol >= 0) && (gcol < WW);
            int gys = min(max(gy, 0), HH - 1);
            int gcs = min(max(gcol, 0), WW - 4);
            const float* src = in + (cb + ch) * HW + gys * WW + gcs;
            unsigned dst = smem_u32(&s_in[b][ch * CHF + r * TW + ck * 4]);
            cp16z(dst, src, ok ? 16 : 0);
        }
        // weights: NC x 10oc x 9, interleaved [c][pr][k][par]
        #pragma unroll
        for (int i = tid; i < NC * 90; i += 256) {
            int c = i / 90;
            int rem = i - c * 90;
            int o = rem / 9;
            int k = rem - o * 9;
            const float* src = wgt + (ocb + o) * 900 + (cb + c) * 9 + k;
            unsigned dst = smem_u32(&s_w[b][c * 90 + (o >> 1) * 18 + k * 2 + (o & 1)]);
            cp4(dst, src);
        }
        cp_commit();
    };

    stage(0, 0);
    int buf = 0;

    for (int it = 0; it < 25; it++) {
        if (it < 24) {
            stage(buf ^ 1, (it + 1) * NC);
            cp_wait<1>();
        } else {
            cp_wait<0>();
        }
        __syncthreads();

        const float* sw = s_w[buf];
        #pragma unroll
        for (int c = 0; c < NC; c++) {
            const float* si = s_in[buf] + c * CHF + (ty * 4) * TW + tx + 3;
            u64 vd[18];
            #pragma unroll
            for (int r = 0; r < 6; r++)
                #pragma unroll
                for (int kx = 0; kx < 3; kx++) {
                    float v = si[r * TW + kx];
                    vd[r * 3 + kx] = pack2(v, v);
                }
            const u64* wp = (const u64*)(sw + c * 90);
            #pragma unroll
            for (int pr = 0; pr < 5; pr++) {
                #pragma unroll
                for (int k = 0; k < 9; k++) {
                    u64 w2 = wp[pr * 9 + k];
                    ffma2(acc[pr * 4 + 0], w2, vd[k]);
                    ffma2(acc[pr * 4 + 1], w2, vd[k + 3]);
                    ffma2(acc[pr * 4 + 2], w2, vd[k + 6]);
                    ffma2(acc[pr * 4 + 3], w2, vd[k + 9]);
                }
            }
        }
        __syncthreads();
        buf ^= 1;
    }

    float m[4];
    #pragma unroll
    for (int px = 0; px < 4; px++) m[px] = mask[(oyb + px) * WW + ox];

    #pragma unroll
    for (int pr = 0; pr < 5; pr++) {
        float a0 = aux[ocb + pr * 2], a1 = aux[ocb + pr * 2 + 1];
        #pragma unroll
        for (int px = 0; px < 4; px++) {
            float v0, v1;
            unpack2(acc[pr * 4 + px], v0, v1);
            if (MODE == 0) {
                v0 = (v0 >= 0.f ? v0 : a0 * v0) * m[px];
                v1 = (v1 >= 0.f ? v1 : a1 * v1) * m[px];
            } else {
                v0 *= m[px]; v1 *= m[px];
                v0 = (v0 >= 0.f ? v0 : a0 * v0);
                v1 = (v1 >= 0.f ? v1 : a1 * v1);
            }
            out[(ocb + pr * 2 + 0) * HW + (oyb + px) * WW + ox] = v0;
            out[(ocb + pr * 2 + 1) * HW + (oyb + px) * WW + ox] = v1;
        }
    }
}

// ---------------------------------------------------------------------------
// Kernel 2b: small scalar 3x3 conv (mask head), CIN=32, OCT=2, bias only
// ---------------------------------------------------------------------------
template <int CIN, int OCT>
__global__ __launch_bounds__(256) void conv3x3_small_kernel(
    const float* __restrict__ in, const float* __restrict__ wgt,
    const float* __restrict__ bias, float* __restrict__ out)
{
    __shared__ float s_in[10 * 34];
    __shared__ float s_w[OCT * 9];

    const int tid = threadIdx.x;
    const int tx = tid & 31;
    const int ty = tid >> 5;
    const int ox0 = blockIdx.x * 32;
    const int oy0 = blockIdx.y * 8;
    const int ox = ox0 + tx, oy = oy0 + ty;

    float acc[OCT];
    #pragma unroll
    for (int o = 0; o < OCT; o++) acc[o] = 0.f;

    for (int ci = 0; ci < CIN; ci++) {
        #pragma unroll
        for (int idx = tid; idx < 340; idx += 256) {
            int r = idx / 34, c = idx - r * 34;
            int gy = oy0 - 1 + r, gx = ox0 - 1 + c;
            float v = 0.f;
            if (gx >= 0 && gx < WW && gy >= 0 && gy < HH)
                v = in[ci * HW + gy * WW + gx];
            s_in[idx] = v;
        }
        if (tid < OCT * 9)
            s_w[tid] = wgt[(tid / 9) * (CIN * 9) + ci * 9 + (tid % 9)];
        __syncthreads();

        float r[9];
        #pragma unroll
        for (int ky = 0; ky < 3; ky++)
            #pragma unroll
            for (int kx = 0; kx < 3; kx++)
                r[ky * 3 + kx] = s_in[(ty + ky) * 34 + tx + kx];

        #pragma unroll
        for (int o = 0; o < OCT; o++) {
            float s = acc[o];
            #pragma unroll
            for (int k = 0; k < 9; k++)
                s = fmaf(s_w[o * 9 + k], r[k], s);
            acc[o] = s;
        }
        __syncthreads();
    }
    #pragma unroll
    for (int o = 0; o < OCT; o++)
        out[o * HW + oy * WW + ox] = acc[o] + bias[o];
}

// ---------------------------------------------------------------------------
// Kernel 3: 1x1 conv 500 -> 36, f32x2, 2 pixels/thread
// ---------------------------------------------------------------------------
__global__ __launch_bounds__(256) void conv1x1_v2_kernel(
    const float* __restrict__ feats, const float* __restrict__ wl,
    const float* __restrict__ bl, float* __restrict__ out)
{
    __shared__ __align__(16) float s_w[100 * 36];  // [ci][pr][par] interleaved
    const int tid = threadIdx.x;
    const int pA = blockIdx.x * 512 + tid;
    const int pB = pA + 256;

    u64 accA[18], accB[18];
    #pragma unroll
    for (int pr = 0; pr < 18; pr++) {
        u64 b2 = pack2(bl[pr * 2], bl[pr * 2 + 1]);
        accA[pr] = b2;
        accB[pr] = b2;
    }

    for (int ch = 0; ch < 5; ch++) {
        __syncthreads();
        for (int i = tid; i < 3600; i += 256) {
            int ci = i / 36, o = i - ci * 36;
            s_w[(ci * 18 + (o >> 1)) * 2 + (o & 1)] = wl[o * 500 + ch * 100 + ci];
        }
        __syncthreads();
        const float* fpA = feats + ch * 100 * HW + pA;
        const float* fpB = feats + ch * 100 * HW + pB;
        #pragma unroll 2
        for (int ci = 0; ci < 100; ci++) {
            float vA = fpA[ci * HW];
            float vB = fpB[ci * HW];
            u64 a2 = pack2(vA, vA);
            u64 b2 = pack2(vB, vB);
            const u64* wp = (const u64*)(s_w + ci * 36);
            #pragma unroll
            for (int pr = 0; pr < 18; pr++) {
                u64 w2 = wp[pr];
                ffma2(accA[pr], w2, a2);
                ffma2(accB[pr], w2, b2);
            }
        }
    }
    #pragma unroll
    for (int pr = 0; pr < 18; pr++) {
        float v0, v1;
        unpack2(accA[pr], v0, v1);
        out[(pr * 2 + 0) * HW + pA] = v0;
        out[(pr * 2 + 1) * HW + pA] = v1;
        unpack2(accB[pr], v0, v1);
        out[(pr * 2 + 0) * HW + pB] = v0;
        out[(pr * 2 + 1) * HW + pB] = v1;
    }
}

// ---------------------------------------------------------------------------
// Kernel 4: 2x bilinear upsample + mask
// ---------------------------------------------------------------------------
__global__ __launch_bounds__(256) void upsample_kernel(
    const float* __restrict__ x36, const float* __restrict__ smn,
    const float* __restrict__ smask, float* __restrict__ out)
{
    int p = blockIdx.x * 256 + threadIdx.x;
    if (p >= OHW) return;
    int oy = p / OW, ox = p - oy * OW;
    int iy = oy >> 1, ix = ox >> 1;

    int r0, r1; float wr0, wr1;
    if (oy & 1) { r0 = iy; r1 = min(iy + 1, HH - 1); wr0 = 0.75f; wr1 = 0.25f; }
    else        { r0 = max(iy - 1, 0); r1 = iy;      wr0 = 0.25f; wr1 = 0.75f; }
    int c0, c1; float wc0, wc1;
    if (ox & 1) { c0 = ix; c1 = min(ix + 1, WW - 1); wc0 = 0.75f; wc1 = 0.25f; }
    else        { c0 = max(ix - 1, 0); c1 = ix;      wc0 = 0.25f; wc1 = 0.75f; }

    int b00 = r0 * WW + c0, b01 = r0 * WW + c1;
    int b10 = r1 * WW + c0, b11 = r1 * WW + c1;

    #pragma unroll 4
    for (int ch = 0; ch < 36; ch++) {
        const float* g = x36 + ch * HW;
        float v = wr0 * (wc0 * g[b00] + wc1 * g[b01]) +
                  wr1 * (wc0 * g[b10] + wc1 * g[b11]);
        out[ch * OHW + p] = v;
    }

    const float* s0p = smn;
    const float* s1p = smn + HW;
    float s0 = wr0 * (wc0 * s0p[b00] + wc1 * s0p[b01]) +
               wr1 * (wc0 * s0p[b10] + wc1 * s0p[b11]);
    float s1 = wr0 * (wc0 * s1p[b00] + wc1 * s1p[b01]) +
               wr1 * (wc0 * s1p[b10] + wc1 * s1p[b11]);
    float mu = smask[iy * WW + ix];
    out[36 * OHW + p] = (s0 > s1) ? mu : 0.f;
}

// ---------------------------------------------------------------------------
// Launcher
// ---------------------------------------------------------------------------
extern "C" void kernel_launch(void* const* d_in, const int* in_sizes, int n_in,
                              void* d_out, int out_size)
{
    const float* feat_0     = (const float*)d_in[0];
    const float* feat_1     = (const float*)d_in[1];
    const float* feat_dense = (const float*)d_in[2];
    const float* flow       = (const float*)d_in[3];
    const float* space_mask = (const float*)d_in[4];
    const float* w_head     = (const float*)d_in[5];
    const float* a_head     = (const float*)d_in[6];
    const float* w_blocks   = (const float*)d_in[7];
    const float* a_blocks   = (const float*)d_in[8];
    const float* w_last     = (const float*)d_in[9];
    const float* b_last     = (const float*)d_in[10];
    const float* w_mask     = (const float*)d_in[11];
    const float* b_mask     = (const float*)d_in[12];

    float *x0, *feats, *x36, *smn;
    cudaGetSymbolAddress((void**)&x0,    g_x0);
    cudaGetSymbolAddress((void**)&feats, g_feats);
    cudaGetSymbolAddress((void**)&x36,   g_x36);
    cudaGetSymbolAddress((void**)&smn,   g_smn);

    warp_concat_kernel<<<196, 256>>>(feat_0, feat_1, feat_dense, flow);

    dim3 cgrid(7, 7, 10);   // 32x32 tiles, 10 oc per z
    conv3x3_v2_kernel<0><<<cgrid, 256>>>(
        x0, w_head, a_head, space_mask, feats);
    for (int i = 0; i < 4; i++) {
        conv3x3_v2_kernel<1><<<cgrid, 256>>>(
            feats + i * 100 * HW,
            w_blocks + i * 100 * 100 * 9,
            a_blocks + i * 100,
            space_mask,
            feats + (i + 1) * 100 * HW);
    }

    conv1x1_v2_kernel<<<98, 256>>>(feats, w_last, b_last, x36);

    conv3x3_small_kernel<32, 2><<<dim3(7, 28, 1), 256>>>(
        x36 + 4 * HW, w_mask, b_mask, smn);

    upsample_kernel<<<784, 256>>>(x36, smn, space_mask, (float*)d_out);
}

// round 5
// speedup vs baseline: 3.6553x; 1.7038x over previous
#include <cuda_runtime.h>
#include <cuda_bf16.h>
#include <cstdint>

#define HH 224
#define WW 224
#define HW (HH*WW)
#define OH 448
#define OW 448
#define OHW (OH*OW)

typedef unsigned int u32;
typedef unsigned long long u64;

// ---------------------------------------------------------------------------
// Scratch: activations pixel-major packed (bf16 hi | bf16 lo<<16)
// ---------------------------------------------------------------------------
__device__ u32  act2_x0[HW * 100];
__device__ u32  act2_feats[5 * HW * 100];
__device__ float g_x36[36 * HW];
__device__ float g_smn[2 * HW];
// weight images: [5 layers][9 kpos][2 splits][112 oc x 120 ci-stride] bf16
__device__ __align__(16) __nv_bfloat16 g_wimg[5 * 9 * 2 * 13440];

// ---------------------------------------------------------------------------
// helpers
// ---------------------------------------------------------------------------
__device__ __forceinline__ u32 smem_u32(const void* p) {
    u32 r;
    asm("{ .reg .u64 t; cvta.to.shared.u64 t, %1; cvt.u32.u64 %0, t; }"
        : "=r"(r) : "l"(p));
    return r;
}
__device__ __forceinline__ void cp16(u32 dst, const void* src) {
    asm volatile("cp.async.cg.shared.global [%0], [%1], 16;"
                 :: "r"(dst), "l"(src));
}
__device__ __forceinline__ void cp_commit() { asm volatile("cp.async.commit_group;"); }
__device__ __forceinline__ void cp_wait0()  { asm volatile("cp.async.wait_group 0;"); }
__device__ __forceinline__ void cp_wait1()  { asm volatile("cp.async.wait_group 1;"); }

__device__ __forceinline__ void ldsm4(u32* r, u32 addr) {
    asm volatile("ldmatrix.sync.aligned.m8n8.x4.shared.b16 {%0,%1,%2,%3}, [%4];"
        : "=r"(r[0]), "=r"(r[1]), "=r"(r[2]), "=r"(r[3]) : "r"(addr));
}
__device__ __forceinline__ void mma16816(float* c, const u32* a, u32 b0, u32 b1) {
    asm volatile("mma.sync.aligned.m16n8k16.row.col.f32.bf16.bf16.f32 "
        "{%0,%1,%2,%3}, {%4,%5,%6,%7}, {%8,%9}, {%0,%1,%2,%3};"
        : "+f"(c[0]), "+f"(c[1]), "+f"(c[2]), "+f"(c[3])
        : "r"(a[0]), "r"(a[1]), "r"(a[2]), "r"(a[3]), "r"(b0), "r"(b1));
}

// pack/unpack fp32 <-> (bf16 hi in low16 | bf16 lo in high16)
__device__ __forceinline__ u32 pack_hl(float v) {
    __nv_bfloat16 h = __float2bfloat16(v);
    float fh = __bfloat162float(h);
    __nv_bfloat16 l = __float2bfloat16(v - fh);
    return (u32)__bfloat16_as_ushort(h) | ((u32)__bfloat16_as_ushort(l) << 16);
}
__device__ __forceinline__ float unpack_hl(u32 b) {
    return __uint_as_float(b << 16) + __uint_as_float(b & 0xFFFF0000u);
}

// f32x2
__device__ __forceinline__ u64 pack2f(float lo, float hi) {
    u64 r; asm("mov.b64 %0, {%1, %2};" : "=l"(r) : "f"(lo), "f"(hi)); return r;
}
__device__ __forceinline__ void unpack2f(u64 v, float& lo, float& hi) {
    asm("mov.b64 {%0, %1}, %2;" : "=f"(lo), "=f"(hi) : "l"(v));
}
__device__ __forceinline__ void ffma2(u64& acc, u64 a, u64 b) {
    asm("fma.rn.f32x2 %0, %1, %2, %0;" : "+l"(acc) : "l"(a), "l"(b));
}

// ---------------------------------------------------------------------------
// Prep: weight images. grid = 45 (layer*9 + kpos)
// Per kpos: hi split [112x120] then lo split, row-major, 120-elem ci stride.
// ---------------------------------------------------------------------------
__global__ __launch_bounds__(256) void prep_weights_kernel(
    const float* __restrict__ w_head, const float* __restrict__ w_blocks)
{
    int l = blockIdx.x / 9, kp = blockIdx.x - 9 * (blockIdx.x / 9);
    const float* src = (l == 0) ? w_head : (w_blocks + (l - 1) * 90000);
    __nv_bfloat16* dhi = g_wimg + (size_t)(l * 9 + kp) * 26880;
    __nv_bfloat16* dlo = dhi + 13440;
    for (int i = threadIdx.x; i < 13440; i += 256) {
        int m = i / 120, k = i - 120 * (i / 120);
        float wv = (m < 100 && k < 100) ? src[m * 900 + k * 9 + kp] : 0.f;
        __nv_bfloat16 h = __float2bfloat16(wv);
        __nv_bfloat16 lo = __float2bfloat16(wv - __bfloat162float(h));
        dhi[i] = h;
        dlo[i] = lo;
    }
}

// ---------------------------------------------------------------------------
// Kernel 1: warp + concat -> act2_x0 [p][100]
// ---------------------------------------------------------------------------
__global__ __launch_bounds__(256) void warp_concat_kernel(
    const float* __restrict__ f0, const float* __restrict__ f1,
    const float* __restrict__ fd, const float* __restrict__ flow)
{
    int p = blockIdx.x * 256 + threadIdx.x;
    if (p >= HW) return;
    int y = p / WW, x = p - y * WW;
    u32* row = act2_x0 + (size_t)p * 100;

    #pragma unroll 4
    for (int c = 0; c < 32; c++) row[64 + c] = pack_hl(fd[c * HW + p]);
    #pragma unroll
    for (int c = 0; c < 4; c++)  row[96 + c] = pack_hl(flow[c * HW + p]);

    #pragma unroll
    for (int pair = 0; pair < 2; pair++) {
        const float* img = (pair == 0) ? f0 : f1;
        float px = (float)x + flow[(pair * 2 + 0) * HW + p];
        float py = (float)y + flow[(pair * 2 + 1) * HW + p];
        float fx = floorf(px), fy = floorf(py);
        float wx = px - fx, wy = py - fy;
        int ix = (int)fminf(fmaxf(fx, -2.f), 226.f);
        int iy = (int)fminf(fmaxf(fy, -2.f), 226.f);
        int x0i = min(max(ix, 0), WW - 1);
        int x1i = min(max(ix + 1, 0), WW - 1);
        int y0i = min(max(iy, 0), HH - 1);
        int y1i = min(max(iy + 1, 0), HH - 1);
        float w00 = (1.f - wx) * (1.f - wy);
        float w01 = wx * (1.f - wy);
        float w10 = (1.f - wx) * wy;
        float w11 = wx * wy;
        int b00 = y0i * WW + x0i, b01 = y0i * WW + x1i;
        int b10 = y1i * WW + x0i, b11 = y1i * WW + x1i;
        #pragma unroll 4
        for (int c = 0; c < 32; c++) {
            const float* g = img + c * HW;
            float v = g[b00] * w00 + g[b01] * w01 + g[b10] * w10 + g[b11] * w11;
            row[pair * 32 + c] = pack_hl(v);
        }
    }
}

// ---------------------------------------------------------------------------
// Kernel 2: HMMA implicit-GEMM 3x3 conv.
// CTA: 128 px x 112 oc. 8 warps, each full-M x 16 px.
// Split bf16 hi/lo, 3 products, fp32 accum.
// ---------------------------------------------------------------------------
#define WSTRIDE 240       // A smem row stride bytes (120 halves)
#define SPLIT_B 26880     // bytes per split
#define KPOS_B  53760     // bytes per kpos stage
#define CONV_DSMEM (2 * KPOS_B)

__device__ __forceinline__ void loadB(u32* b, const u32* r0, const u32* r1,
                                      bool ok0, bool ok1, int ci) {
    #pragma unroll
    for (int nf = 0; nf < 2; nf++) {
        const u32* r = nf ? r1 : r0;
        bool ok = nf ? ok1 : ok0;
        u32 v0 = 0, v1 = 0, w0 = 0, w1 = 0;
        if (ok && ci <= 98)     { uint2 t = *(const uint2*)(r + ci);     v0 = t.x; v1 = t.y; }
        if (ok && ci + 8 <= 98) { uint2 t = *(const uint2*)(r + ci + 8); w0 = t.x; w1 = t.y; }
        b[nf * 4 + 0] = __byte_perm(v0, v1, 0x5410);  // hi pair k,k+1
        b[nf * 4 + 1] = __byte_perm(w0, w1, 0x5410);  // hi pair k+8,k+9
        b[nf * 4 + 2] = __byte_perm(v0, v1, 0x7632);  // lo pair
        b[nf * 4 + 3] = __byte_perm(w0, w1, 0x7632);
    }
}

template <int MODE>
__global__ __launch_bounds__(256, 1) void conv_hmma_kernel(
    const u32* __restrict__ in,                 // [HW][100]
    const __nv_bfloat16* __restrict__ wimg,     // layer base, [9][2][13440]
    const float* __restrict__ aux,
    const float* __restrict__ mask,
    u32* __restrict__ outp)                     // [HW][100]
{
    extern __shared__ __align__(16) char dsm[];
    __shared__ float s_mask[128];
    __shared__ float s_aux[112];

    const int tid = threadIdx.x;
    const int w = tid >> 5;
    const int lid = tid & 31;
    const int pixbase = blockIdx.x << 7;

    if (tid < 128) s_mask[tid] = mask[pixbase + tid];
    if (tid < 112) s_aux[tid] = (tid < 100) ? aux[tid] : 0.f;

    const u32 sb = smem_u32(dsm);

    const int p0 = pixbase + w * 16 + (lid >> 2);
    const int p1 = p0 + 8;
    const int py0 = p0 / WW, px0 = p0 - py0 * WW;
    const int py1 = p1 / WW, px1 = p1 - py1 * WW;

    float acc[7][2][4];
    #pragma unroll
    for (int m = 0; m < 7; m++)
        #pragma unroll
        for (int nf = 0; nf < 2; nf++)
            #pragma unroll
            for (int i = 0; i < 4; i++) acc[m][nf][i] = 0.f;

    // prologue: stage kpos 0 into buf 0
    {
        const char* src = (const char*)wimg;
        for (int i = tid; i < 3360; i += 256) cp16(sb + i * 16, src + i * 16);
        cp_commit();
    }

    const int cib = (lid & 3) * 2;
    const u32 arow = (lid & 15) * WSTRIDE + (lid >> 4) * 16;

    for (int kp = 0; kp < 9; kp++) {
        const int buf = kp & 1;
        const u32 bufaddr = sb + buf * KPOS_B;

        if (kp < 8) {
            const char* src = (const char*)wimg + (size_t)(kp + 1) * KPOS_B;
            u32 dst = sb + (buf ^ 1) * KPOS_B;
            for (int i = tid; i < 3360; i += 256) cp16(dst + i * 16, src + i * 16);
            cp_commit();
            cp_wait1();
        } else {
            cp_wait0();
        }
        __syncthreads();

        const int ky = kp / 3, kx = kp - 3 * (kp / 3);
        const int iy0 = py0 + ky - 1, ix0 = px0 + kx - 1;
        const int iy1 = py1 + ky - 1, ix1 = px1 + kx - 1;
        const bool ok0 = (iy0 >= 0) & (iy0 < HH) & (ix0 >= 0) & (ix0 < WW);
        const bool ok1 = (iy1 >= 0) & (iy1 < HH) & (ix1 >= 0) & (ix1 < WW);
        const u32* r0 = in + (size_t)(iy0 * WW + ix0) * 100;
        const u32* r1 = in + (size_t)(iy1 * WW + ix1) * 100;

        u32 bc[8], bn[8];
        loadB(bc, r0, r1, ok0, ok1, cib);

        #pragma unroll
        for (int ks = 0; ks < 7; ks++) {
            if (ks < 6) loadB(bn, r0, r1, ok0, ok1, cib + (ks + 1) * 16);
            const u32 kaddr = bufaddr + arow + ks * 32;
            #pragma unroll
            for (int m = 0; m < 7; m++) {
                u32 ah[4], al[4];
                ldsm4(ah, kaddr + m * 3840);
                ldsm4(al, kaddr + m * 3840 + SPLIT_B);
                #pragma unroll
                for (int nf = 0; nf < 2; nf++) {
                    mma16816(acc[m][nf], ah, bc[nf * 4 + 0], bc[nf * 4 + 1]); // hh
                    mma16816(acc[m][nf], ah, bc[nf * 4 + 2], bc[nf * 4 + 3]); // h*l
                    mma16816(acc[m][nf], al, bc[nf * 4 + 0], bc[nf * 4 + 1]); // l*h
                }
            }
            #pragma unroll
            for (int q = 0; q < 8; q++) bc[q] = bn[q];
        }
        __syncthreads();
    }

    // epilogue: transform + smem transpose + coalesced store
    u32* tr = (u32*)dsm;      // [128 px][stride 116] u32
    #pragma unroll
    for (int m = 0; m < 7; m++) {
        const int oc0 = m * 16 + (lid >> 2);
        #pragma unroll
        for (int nf = 0; nf < 2; nf++) {
            const int pxc = w * 16 + nf * 8 + (lid & 3) * 2;
            #pragma unroll
            for (int i = 0; i < 4; i++) {
                const int oc = oc0 + (i >> 1) * 8;
                const int px = pxc + (i & 1);
                if (oc < 100) {
                    float v = acc[m][nf][i];
                    float a = s_aux[oc], mm = s_mask[px];
                    if (MODE == 0) {
                        v = (v >= 0.f ? v : a * v) * mm;
                    } else {
                        v *= mm;
                        v = (v >= 0.f ? v : a * v);
                    }
                    tr[px * 116 + oc] = pack_hl(v);
                }
            }
        }
    }
    __syncthreads();
    for (int i = tid; i < 12800; i += 256) {
        int px = i / 100, ci = i - 100 * (i / 100);
        outp[(size_t)(pixbase + px) * 100 + ci] = tr[px * 116 + ci];
    }
}

// ---------------------------------------------------------------------------
// Kernel 3: 1x1 conv 500 -> 36, f32x2, pixel-major packed input
// ---------------------------------------------------------------------------
__global__ __launch_bounds__(256) void conv1x1_kernel(
    const u32* __restrict__ feats, const float* __restrict__ wl,
    const float* __restrict__ bl, float* __restrict__ out)
{
    __shared__ __align__(16) float s_w[3600];
    const int tid = threadIdx.x;
    const size_t p = (size_t)blockIdx.x * 256 + tid;

    u64 acc[18];
    #pragma unroll
    for (int pr = 0; pr < 18; pr++) acc[pr] = pack2f(bl[pr * 2], bl[pr * 2 + 1]);

    for (int ch = 0; ch < 5; ch++) {
        __syncthreads();
        for (int i = tid; i < 3600; i += 256) {
            int ci = i / 36, o = i - ci * 36;
            s_w[(ci * 18 + (o >> 1)) * 2 + (o & 1)] = wl[o * 500 + ch * 100 + ci];
        }
        __syncthreads();
        const uint4* row = (const uint4*)(feats + ((size_t)ch * HW + p) * 100);
        #pragma unroll 5
        for (int g = 0; g < 25; g++) {
            uint4 q = row[g];
            u32 vv[4] = {q.x, q.y, q.z, q.w};
            #pragma unroll
            for (int j = 0; j < 4; j++) {
                float f = unpack_hl(vv[j]);
                u64 f2 = pack2f(f, f);
                const u64* wp = (const u64*)(s_w + (g * 4 + j) * 36);
                #pragma unroll
                for (int pr = 0; pr < 18; pr++) ffma2(acc[pr], wp[pr], f2);
            }
        }
    }
    #pragma unroll
    for (int pr = 0; pr < 18; pr++) {
        float v0, v1;
        unpack2f(acc[pr], v0, v1);
        out[(pr * 2 + 0) * HW + p] = v0;
        out[(pr * 2 + 1) * HW + p] = v1;
    }
}

// ---------------------------------------------------------------------------
// Kernel 2b: small 3x3 conv (mask head), 32 -> 2, bias
// ---------------------------------------------------------------------------
__global__ __launch_bounds__(256) void conv3x3_small_kernel(
    const float* __restrict__ in, const float* __restrict__ wgt,
    const float* __restrict__ bias, float* __restrict__ out)
{
    __shared__ float s_in[10 * 34];
    __shared__ float s_w[2 * 9];

    const int tid = threadIdx.x;
    const int tx = tid & 31;
    const int ty = tid >> 5;
    const int ox0 = blockIdx.x * 32;
    const int oy0 = blockIdx.y * 8;
    const int ox = ox0 + tx, oy = oy0 + ty;

    float acc0 = 0.f, acc1 = 0.f;

    for (int ci = 0; ci < 32; ci++) {
        #pragma unroll
        for (int idx = tid; idx < 340; idx += 256) {
            int r = idx / 34, c = idx - r * 34;
            int gy = oy0 - 1 + r, gx = ox0 - 1 + c;
            float v = 0.f;
            if (gx >= 0 && gx < WW && gy >= 0 && gy < HH)
                v = in[ci * HW + gy * WW + gx];
            s_in[idx] = v;
        }
        if (tid < 18)
            s_w[tid] = wgt[(tid / 9) * (32 * 9) + ci * 9 + (tid % 9)];
        __syncthreads();

        float r[9];
        #pragma unroll
        for (int ky = 0; ky < 3; ky++)
            #pragma unroll
            for (int kx = 0; kx < 3; kx++)
                r[ky * 3 + kx] = s_in[(ty + ky) * 34 + tx + kx];

        #pragma unroll
        for (int k = 0; k < 9; k++) {
            acc0 = fmaf(s_w[k], r[k], acc0);
            acc1 = fmaf(s_w[9 + k], r[k], acc1);
        }
        __syncthreads();
    }
    out[oy * WW + ox] = acc0 + bias[0];
    out[HW + oy * WW + ox] = acc1 + bias[1];
}

// ---------------------------------------------------------------------------
// Kernel 4: 2x bilinear upsample + mask
// ---------------------------------------------------------------------------
__global__ __launch_bounds__(256) void upsample_kernel(
    const float* __restrict__ x36, const float* __restrict__ smn,
    const float* __restrict__ smask, float* __restrict__ out)
{
    int p = blockIdx.x * 256 + threadIdx.x;
    if (p >= OHW) return;
    int oy = p / OW, ox = p - oy * OW;
    int iy = oy >> 1, ix = ox >> 1;

    int r0, r1; float wr0, wr1;
    if (oy & 1) { r0 = iy; r1 = min(iy + 1, HH - 1); wr0 = 0.75f; wr1 = 0.25f; }
    else        { r0 = max(iy - 1, 0); r1 = iy;      wr0 = 0.25f; wr1 = 0.75f; }
    int c0, c1; float wc0, wc1;
    if (ox & 1) { c0 = ix; c1 = min(ix + 1, WW - 1); wc0 = 0.75f; wc1 = 0.25f; }
    else        { c0 = max(ix - 1, 0); c1 = ix;      wc0 = 0.25f; wc1 = 0.75f; }

    int b00 = r0 * WW + c0, b01 = r0 * WW + c1;
    int b10 = r1 * WW + c0, b11 = r1 * WW + c1;

    #pragma unroll 4
    for (int ch = 0; ch < 36; ch++) {
        const float* g = x36 + ch * HW;
        float v = wr0 * (wc0 * g[b00] + wc1 * g[b01]) +
                  wr1 * (wc0 * g[b10] + wc1 * g[b11]);
        out[ch * OHW + p] = v;
    }

    const float* s0p = smn;
    const float* s1p = smn + HW;
    float s0 = wr0 * (wc0 * s0p[b00] + wc1 * s0p[b01]) +
               wr1 * (wc0 * s0p[b10] + wc1 * s0p[b11]);
    float s1 = wr0 * (wc0 * s1p[b00] + wc1 * s1p[b01]) +
               wr1 * (wc0 * s1p[b10] + wc1 * s1p[b11]);
    float mu = smask[iy * WW + ix];
    out[36 * OHW + p] = (s0 > s1) ? mu : 0.f;
}

// ---------------------------------------------------------------------------
// Launcher
// ---------------------------------------------------------------------------
extern "C" void kernel_launch(void* const* d_in, const int* in_sizes, int n_in,
                              void* d_out, int out_size)
{
    const float* feat_0     = (const float*)d_in[0];
    const float* feat_1     = (const float*)d_in[1];
    const float* feat_dense = (const float*)d_in[2];
    const float* flow       = (const float*)d_in[3];
    const float* space_mask = (const float*)d_in[4];
    const float* w_head     = (const float*)d_in[5];
    const float* a_head     = (const float*)d_in[6];
    const float* w_blocks   = (const float*)d_in[7];
    const float* a_blocks   = (const float*)d_in[8];
    const float* w_last     = (const float*)d_in[9];
    const float* b_last     = (const float*)d_in[10];
    const float* w_mask     = (const float*)d_in[11];
    const float* b_mask     = (const float*)d_in[12];

    u32 *x0a, *featsa;
    float *x36, *smn;
    __nv_bfloat16* wimg;
    cudaGetSymbolAddress((void**)&x0a,    act2_x0);
    cudaGetSymbolAddress((void**)&featsa, act2_feats);
    cudaGetSymbolAddress((void**)&x36,    g_x36);
    cudaGetSymbolAddress((void**)&smn,    g_smn);
    cudaGetSymbolAddress((void**)&wimg,   g_wimg);

    cudaFuncSetAttribute(conv_hmma_kernel<0>,
                         cudaFuncAttributeMaxDynamicSharedMemorySize, CONV_DSMEM);
    cudaFuncSetAttribute(conv_hmma_kernel<1>,
                         cudaFuncAttributeMaxDynamicSharedMemorySize, CONV_DSMEM);

    prep_weights_kernel<<<45, 256>>>(w_head, w_blocks);
    warp_concat_kernel<<<196, 256>>>(feat_0, feat_1, feat_dense, flow);

    conv_hmma_kernel<0><<<392, 256, CONV_DSMEM>>>(
        x0a, wimg, a_head, space_mask, featsa);
    for (int i = 1; i < 5; i++) {
        conv_hmma_kernel<1><<<392, 256, CONV_DSMEM>>>(
            featsa + (size_t)(i - 1) * HW * 100,
            wimg + (size_t)i * 9 * 26880,
            a_blocks + (i - 1) * 100,
            space_mask,
            featsa + (size_t)i * HW * 100);
    }

    conv1x1_kernel<<<196, 256>>>(featsa, w_last, b_last, x36);

    conv3x3_small_kernel<<<dim3(7, 28, 1), 256>>>(
        x36 + 4 * HW, w_mask, b_mask, smn);

    upsample_kernel<<<784, 256>>>(x36, smn, space_mask, (float*)d_out);
}